// round 4
// baseline (speedup 1.0000x reference)
#include <cuda_runtime.h>
#include <cstdint>
#include <math.h>

// Problem constants
#define BATCH 8
#define SEQ   4096
#define DMODEL 512
#define NSTATE 64
#define TOKENS (BATCH*SEQ)          // 32768
#define NCHUNKS 16
#define CHUNK  (SEQ/NCHUNKS)        // 256
#define LN_EPS 1e-3f

// ---------------- device scratch ----------------
__device__ float g_xn [ (size_t)TOKENS * DMODEL ];   // LN output, tf32-rounded
__device__ float g_xp [ (size_t)TOKENS * DMODEL ];   // in-proj, tf32-rounded (GEMM2 A)
__device__ float g_xpf[ (size_t)TOKENS * DMODEL ];   // in-proj, full precision (GEMM3 aux)
__device__ float g_bcx[ (size_t)TOKENS * 192 ];      // [B|C|xs], full precision (scan)
__device__ float g_ch [ (size_t)TOKENS * NSTATE ];   // C*h, tf32-rounded (GEMM3 A)
__device__ float g_y1 [ (size_t)TOKENS * DMODEL ];   // pre-out-proj, tf32-rounded (GEMM4 A)
__device__ float g_WTin [ DMODEL * DMODEL ];   // W_in^T, tf32-rounded
__device__ float g_WTcat[ 192 * DMODEL ];      // [B|C|xs]^T, tf32-rounded
__device__ float g_WTso [ DMODEL * NSTATE ];   // W_so^T, tf32-rounded
__device__ float g_WTout[ DMODEL * DMODEL ];   // W_out^T, tf32-rounded
__device__ float g_bcat [ 192 ];
__device__ float g_chunkend[ BATCH * NCHUNKS * NSTATE ];
__device__ float g_hinit   [ BATCH * NCHUNKS * NSTATE ];

// ---------------- PTX helpers ----------------
__device__ __forceinline__ uint32_t smem_u32(const void* p) {
    uint32_t a;
    asm("{ .reg .u64 t; cvta.to.shared.u64 t, %1; cvt.u32.u64 %0, t; }" : "=r"(a) : "l"(p));
    return a;
}
__device__ __forceinline__ void cp16(uint32_t dst, const void* src) {
    asm volatile("cp.async.cg.shared.global [%0], [%1], 16;" :: "r"(dst), "l"(src));
}
#define CP_COMMIT()  asm volatile("cp.async.commit_group;" ::: "memory")
#define CP_WAIT1()   asm volatile("cp.async.wait_group 1;" ::: "memory")

__device__ __forceinline__ float f2tf32(float f) {
    uint32_t r;
    asm("cvt.rna.tf32.f32 %0, %1;" : "=r"(r) : "f"(f));
    return __uint_as_float(r);
}
__device__ __forceinline__ void mma8(float* d, uint32_t a0, uint32_t a1, uint32_t a2,
                                     uint32_t a3, uint32_t b0, uint32_t b1) {
    asm volatile(
        "mma.sync.aligned.m16n8k8.row.col.f32.tf32.tf32.f32 "
        "{%0,%1,%2,%3}, {%4,%5,%6,%7}, {%8,%9}, {%0,%1,%2,%3};"
        : "+f"(d[0]), "+f"(d[1]), "+f"(d[2]), "+f"(d[3])
        : "r"(a0), "r"(a1), "r"(a2), "r"(a3), "r"(b0), "r"(b1));
}

// ---------------- tf32 mma.sync GEMM ----------------
// C[M, N] = A[M, K] @ BT[:, K]^T + epilogue; CTA tile BM=128 x BN, BK=32, 3-stage cp.async
// Operands A, BT must ALREADY be tf32-rounded (raw LDS -> HMMA, no cvt in loop).
// EPI 0: + bias[col]
// EPI 1: + bias[col] * aux[row,col]
// EPI 2: + bias[col] + aux[row,col]
// RND:  round stored C values to tf32 (when C feeds a later GEMM as A operand)
// DUP:  additionally store the full-precision values to C2
template<int BN, int EPI, int RND, int DUP>
__global__ void __launch_bounds__(256, 2)
mma_gemm(const float* __restrict__ A, const float* __restrict__ BT,
         float* __restrict__ C, float* __restrict__ C2,
         const float* __restrict__ bias, const float* __restrict__ aux,
         int K, int N) {
    constexpr int BM = 128, BK = 32, ST = 3, PAD = 36;
    constexpr int WN = BN / 4;       // warp tile N
    constexpr int NT = WN / 8;       // n-subtiles per warp
    extern __shared__ float smf[];
    float* As = smf;                       // ST * BM * PAD
    float* Bs = smf + ST * BM * PAD;       // ST * BN * PAD

    const int tid  = threadIdx.x;
    const int lane = tid & 31;
    const int wid  = tid >> 5;
    const int wm   = wid & 1;        // warp row (0..1) -> 64 rows each
    const int wn   = wid >> 1;       // warp col (0..3) -> WN cols each
    const int g    = lane >> 2;
    const int t    = lane & 3;
    const int m0   = blockIdx.y * BM;
    const int n0   = blockIdx.x * BN;
    const int S    = K / BK;

    const uint32_t asu = smem_u32(As);
    const uint32_t bsu = smem_u32(Bs);

    auto load_stage = [&](int s) {
        int buf = s % ST;
        uint32_t dA = asu + buf * BM * PAD * 4;
        uint32_t dB = bsu + buf * BN * PAD * 4;
        int k0 = s * BK;
        #pragma unroll
        for (int it = 0; it < 4; it++) {
            int i = tid + it * 256;          // 0..1023
            int row = i >> 3, c = i & 7;
            cp16(dA + row * PAD * 4 + c * 16,
                 A + (size_t)(m0 + row) * K + k0 + c * 4);
        }
        #pragma unroll
        for (int it = 0; it < BN / 32; it++) {
            int i = tid + it * 256;
            int row = i >> 3, c = i & 7;
            cp16(dB + row * PAD * 4 + c * 16,
                 BT + (size_t)(n0 + row) * K + k0 + c * 4);
        }
        CP_COMMIT();
    };

    float d[4][NT][4];
    #pragma unroll
    for (int mt = 0; mt < 4; mt++)
        #pragma unroll
        for (int nt = 0; nt < NT; nt++)
            #pragma unroll
            for (int j = 0; j < 4; j++) d[mt][nt][j] = 0.0f;

    load_stage(0);
    load_stage(1);

    for (int s = 0; s < S; s++) {
        CP_WAIT1();
        __syncthreads();
        if (s + 2 < S) load_stage(s + 2); else CP_COMMIT();

        int buf = s % ST;
        const uint32_t* ap = reinterpret_cast<const uint32_t*>(As)
                           + buf * BM * PAD + (wm * 64 + g) * PAD + t;
        const uint32_t* bp = reinterpret_cast<const uint32_t*>(Bs)
                           + buf * BN * PAD + (wn * WN + g) * PAD + t;
        #pragma unroll
        for (int kk = 0; kk < 4; kk++) {
            int ko = kk * 8;
            uint32_t af[4][4];
            #pragma unroll
            for (int mt = 0; mt < 4; mt++) {
                af[mt][0] = ap[(mt * 16    ) * PAD + ko    ];
                af[mt][1] = ap[(mt * 16 + 8) * PAD + ko    ];
                af[mt][2] = ap[(mt * 16    ) * PAD + ko + 4];
                af[mt][3] = ap[(mt * 16 + 8) * PAD + ko + 4];
            }
            uint32_t bf[NT][2];
            #pragma unroll
            for (int nt = 0; nt < NT; nt++) {
                bf[nt][0] = bp[nt * 8 * PAD + ko    ];
                bf[nt][1] = bp[nt * 8 * PAD + ko + 4];
            }
            #pragma unroll
            for (int mt = 0; mt < 4; mt++)
                #pragma unroll
                for (int nt = 0; nt < NT; nt++)
                    mma8(d[mt][nt], af[mt][0], af[mt][1], af[mt][2], af[mt][3],
                         bf[nt][0], bf[nt][1]);
        }
    }

    // ---- epilogue ----
    #pragma unroll
    for (int mt = 0; mt < 4; mt++) {
        int row = m0 + wm * 64 + mt * 16 + g;
        #pragma unroll
        for (int nt = 0; nt < NT; nt++) {
            int col = n0 + wn * WN + nt * 8 + 2 * t;
            float2 b2 = *reinterpret_cast<const float2*>(bias + col);
            size_t off0 = (size_t)row * N + col;
            size_t off1 = (size_t)(row + 8) * N + col;
            float2 v0 = make_float2(d[mt][nt][0], d[mt][nt][1]);
            float2 v1 = make_float2(d[mt][nt][2], d[mt][nt][3]);
            if (EPI == 0) {
                v0.x += b2.x; v0.y += b2.y;
                v1.x += b2.x; v1.y += b2.y;
            } else if (EPI == 1) {
                float2 a0 = *reinterpret_cast<const float2*>(aux + off0);
                float2 a1 = *reinterpret_cast<const float2*>(aux + off1);
                v0.x += b2.x * a0.x; v0.y += b2.y * a0.y;
                v1.x += b2.x * a1.x; v1.y += b2.y * a1.y;
            } else {
                float2 a0 = *reinterpret_cast<const float2*>(aux + off0);
                float2 a1 = *reinterpret_cast<const float2*>(aux + off1);
                v0.x += b2.x + a0.x; v0.y += b2.y + a0.y;
                v1.x += b2.x + a1.x; v1.y += b2.y + a1.y;
            }
            if (DUP) {
                *reinterpret_cast<float2*>(C2 + off0) = v0;
                *reinterpret_cast<float2*>(C2 + off1) = v1;
            }
            if (RND) {
                v0.x = f2tf32(v0.x); v0.y = f2tf32(v0.y);
                v1.x = f2tf32(v1.x); v1.y = f2tf32(v1.y);
            }
            *reinterpret_cast<float2*>(C + off0) = v0;
            *reinterpret_cast<float2*>(C + off1) = v1;
        }
    }
}

// ---------------- weight prep: transposes + concat, tf32-rounded ----------------
__global__ void prep_weights(const float* __restrict__ W_in, const float* __restrict__ W_out,
                             const float* __restrict__ W_B, const float* __restrict__ W_C,
                             const float* __restrict__ W_xs, const float* __restrict__ W_so,
                             const float* __restrict__ b_B, const float* __restrict__ b_C) {
    int idx = blockIdx.x * 256 + threadIdx.x;
    if (idx < DMODEL * DMODEL) {
        int n = idx >> 9, k = idx & 511;
        g_WTin [idx] = f2tf32(W_in [k * DMODEL + n]);
        g_WTout[idx] = f2tf32(W_out[k * DMODEL + n]);
    }
    if (idx < 192 * DMODEL) {
        int n = idx >> 9, k = idx & 511;
        float v;
        if (n < 64)       v = W_B [k * 64 + n];
        else if (n < 128) v = W_C [k * 64 + (n - 64)];
        else              v = W_xs[k * 64 + (n - 128)];
        g_WTcat[idx] = f2tf32(v);
    }
    if (idx < DMODEL * NSTATE) {
        int d = idx >> 6, s = idx & 63;
        g_WTso[idx] = f2tf32(W_so[s * DMODEL + d]);
    }
    if (idx < 192) g_bcat[idx] = (idx < 64) ? b_B[idx] : (idx < 128 ? b_C[idx - 64] : 0.0f);
}

// ---------------- LayerNorm (output tf32-rounded: feeds GEMM1 A) ----------------
__global__ void ln_kernel(const float* __restrict__ x,
                          const float* __restrict__ gamma,
                          const float* __restrict__ beta) {
    int row = blockIdx.x;
    const float4* xr = reinterpret_cast<const float4*>(x) + (size_t)row * 128;
    int t = threadIdx.x;
    float4 v = xr[t];
    float s = v.x + v.y + v.z + v.w;
    float q = v.x*v.x + v.y*v.y + v.z*v.z + v.w*v.w;
    #pragma unroll
    for (int o = 16; o; o >>= 1) {
        s += __shfl_xor_sync(0xffffffffu, s, o);
        q += __shfl_xor_sync(0xffffffffu, q, o);
    }
    __shared__ float ss[4], qq[4];
    int w = t >> 5, l = t & 31;
    if (l == 0) { ss[w] = s; qq[w] = q; }
    __syncthreads();
    s = ss[0] + ss[1] + ss[2] + ss[3];
    q = qq[0] + qq[1] + qq[2] + qq[3];
    float mu  = s * (1.0f / DMODEL);
    float var = q * (1.0f / DMODEL) - mu * mu;
    float inv = rsqrtf(var + LN_EPS);
    float4 gv = reinterpret_cast<const float4*>(gamma)[t];
    float4 bv = reinterpret_cast<const float4*>(beta)[t];
    float4 o;
    o.x = f2tf32((v.x - mu) * inv * gv.x + bv.x);
    o.y = f2tf32((v.y - mu) * inv * gv.y + bv.y);
    o.z = f2tf32((v.z - mu) * inv * gv.z + bv.z);
    o.w = f2tf32((v.w - mu) * inv * gv.w + bv.w);
    reinterpret_cast<float4*>(g_xn)[(size_t)row * 128 + t] = o;
}

// ---------------- chunked SSM scan ----------------
__global__ void scan_passA(const float* __restrict__ A_log) {
    int b = blockIdx.x >> 4;
    int c = blockIdx.x & 15;
    int n = threadIdx.x;
    float Ab = expf(-expf(A_log[n]));
    const float* base = g_bcx + (size_t)(b * SEQ + c * CHUNK) * 192;
    float h = 0.0f;
    #pragma unroll 8
    for (int t = 0; t < CHUNK; t++) {
        float Bv = base[(size_t)t * 192 + n];
        float xv = base[(size_t)t * 192 + 128 + n];
        h = fmaf(Ab, h, Bv * xv);
    }
    g_chunkend[(b * NCHUNKS + c) * NSTATE + n] = h;
}

__global__ void scan_passB(const float* __restrict__ A_log) {
    int idx = threadIdx.x;
    int b = idx / NSTATE;
    int n = idx % NSTATE;
    float AL = expf(-(float)CHUNK * expf(A_log[n]));
    float h = 0.0f;
    for (int c = 0; c < NCHUNKS; c++) {
        g_hinit[(b * NCHUNKS + c) * NSTATE + n] = h;
        h = fmaf(AL, h, g_chunkend[(b * NCHUNKS + c) * NSTATE + n]);
    }
}

// output tf32-rounded: feeds GEMM3 A
__global__ void scan_passC(const float* __restrict__ A_log) {
    int b = blockIdx.x >> 4;
    int c = blockIdx.x & 15;
    int n = threadIdx.x;
    float Ab = expf(-expf(A_log[n]));
    const float* base = g_bcx + (size_t)(b * SEQ + c * CHUNK) * 192;
    float* out = g_ch + (size_t)(b * SEQ + c * CHUNK) * NSTATE;
    float h = g_hinit[(b * NCHUNKS + c) * NSTATE + n];
    #pragma unroll 8
    for (int t = 0; t < CHUNK; t++) {
        float Bv = base[(size_t)t * 192 + n];
        float Cv = base[(size_t)t * 192 + 64 + n];
        float xv = base[(size_t)t * 192 + 128 + n];
        h = fmaf(Ab, h, Bv * xv);
        out[(size_t)t * NSTATE + n] = f2tf32(Cv * h);
    }
}

// ---------------- launch ----------------
extern "C" void kernel_launch(void* const* d_in, const int* in_sizes, int n_in,
                              void* d_out, int out_size) {
    const float* x        = (const float*)d_in[0];
    const float* ln_gamma = (const float*)d_in[1];
    const float* ln_beta  = (const float*)d_in[2];
    const float* W_in     = (const float*)d_in[3];
    const float* b_in     = (const float*)d_in[4];
    const float* W_xs     = (const float*)d_in[5];
    const float* W_B      = (const float*)d_in[6];
    const float* b_B      = (const float*)d_in[7];
    const float* W_C      = (const float*)d_in[8];
    const float* b_C      = (const float*)d_in[9];
    const float* A_log    = (const float*)d_in[10];
    const float* D_skip   = (const float*)d_in[11];
    const float* W_so     = (const float*)d_in[12];
    const float* W_out    = (const float*)d_in[13];
    const float* b_out    = (const float*)d_in[14];
    float* out = (float*)d_out;

    float* xn;    cudaGetSymbolAddress((void**)&xn,    g_xn);
    float* xp;    cudaGetSymbolAddress((void**)&xp,    g_xp);
    float* xpf;   cudaGetSymbolAddress((void**)&xpf,   g_xpf);
    float* bcx;   cudaGetSymbolAddress((void**)&bcx,   g_bcx);
    float* ch;    cudaGetSymbolAddress((void**)&ch,    g_ch);
    float* y1;    cudaGetSymbolAddress((void**)&y1,    g_y1);
    float* WTin;  cudaGetSymbolAddress((void**)&WTin,  g_WTin);
    float* WTcat; cudaGetSymbolAddress((void**)&WTcat, g_WTcat);
    float* WTso;  cudaGetSymbolAddress((void**)&WTso,  g_WTso);
    float* WTout; cudaGetSymbolAddress((void**)&WTout, g_WTout);
    float* bcat;  cudaGetSymbolAddress((void**)&bcat,  g_bcat);

    const int SMEM128 = 3 * (128 + 128) * 36 * 4;   // 110592
    const int SMEM64  = 3 * (128 +  64) * 36 * 4;   //  82944
    cudaFuncSetAttribute(mma_gemm<128, 0, 1, 1>, cudaFuncAttributeMaxDynamicSharedMemorySize, SMEM128);
    cudaFuncSetAttribute(mma_gemm<128, 1, 1, 0>, cudaFuncAttributeMaxDynamicSharedMemorySize, SMEM128);
    cudaFuncSetAttribute(mma_gemm<128, 2, 0, 0>, cudaFuncAttributeMaxDynamicSharedMemorySize, SMEM128);
    cudaFuncSetAttribute(mma_gemm<64, 0, 0, 0>,  cudaFuncAttributeMaxDynamicSharedMemorySize, SMEM64);

    // 1) weight prep (transpose + concat + tf32 round)
    prep_weights<<<(DMODEL * DMODEL + 255) / 256, 256>>>(W_in, W_out, W_B, W_C, W_xs, W_so, b_B, b_C);

    // 2) LayerNorm (tf32-rounded out)
    ln_kernel<<<TOKENS, 128>>>(x, ln_gamma, ln_beta);

    // 3) xp = xn @ W_in + b_in ; writes xp (tf32) + xpf (full)
    mma_gemm<128, 0, 1, 1><<<dim3(4, 256), 256, SMEM128>>>(
        xn, WTin, xp, xpf, b_in, nullptr, DMODEL, DMODEL);

    // 4) [B|C|xs] = xp @ Wcat + bcat   (full precision out, feeds scan)
    mma_gemm<64, 0, 0, 0><<<dim3(3, 256), 256, SMEM64>>>(
        xp, WTcat, bcx, nullptr, bcat, nullptr, DMODEL, 192);

    // 5) chunked scan -> ch = tf32(C * h)
    scan_passA<<<BATCH * NCHUNKS, NSTATE>>>(A_log);
    scan_passB<<<1, BATCH * NSTATE>>>(A_log);
    scan_passC<<<BATCH * NCHUNKS, NSTATE>>>(A_log);

    // 6) y1 = tf32(ch @ W_so + D_skip * xpf)
    mma_gemm<128, 1, 1, 0><<<dim3(4, 256), 256, SMEM128>>>(
        ch, WTso, y1, nullptr, D_skip, xpf, NSTATE, DMODEL);

    // 7) out = y1 @ W_out + b_out + x   (full precision)
    mma_gemm<128, 2, 0, 0><<<dim3(4, 256), 256, SMEM128>>>(
        y1, WTout, out, nullptr, b_out, x, DMODEL, DMODEL);
}

// round 5
// speedup vs baseline: 1.0779x; 1.0779x over previous
#include <cuda_runtime.h>
#include <cstdint>
#include <math.h>

// Problem constants
#define BATCH 8
#define SEQ   4096
#define DMODEL 512
#define NSTATE 64
#define TOKENS (BATCH*SEQ)          // 32768
#define NCHUNKS 16
#define CHUNK  (SEQ/NCHUNKS)        // 256
#define LN_EPS 1e-3f

// K-dim permutation (within groups of 8): fragment pairs (t, t+4) become adjacent
__host__ __device__ __forceinline__ int PERM8(int c) {
    return (c & ~7) | ((c & 3) << 1) | ((c >> 2) & 1);
}
// inverse: position p holds original column INV8(p)
__host__ __device__ __forceinline__ int INV8(int p) {
    return (p & ~7) | ((p & 1) << 2) | ((p >> 1) & 3);
}

// ---------------- device scratch ----------------
__device__ float g_xn [ (size_t)TOKENS * DMODEL ];   // LN out, tf32-rounded, K-permuted
__device__ float g_xp [ (size_t)TOKENS * DMODEL ];   // in-proj, tf32-rounded, K-permuted
__device__ float g_xpf[ (size_t)TOKENS * DMODEL ];   // in-proj, full precision, unpermuted
__device__ float g_bcx[ (size_t)TOKENS * 192 ];      // [B|C|xs], full precision, unpermuted
__device__ float g_ch [ (size_t)TOKENS * NSTATE ];   // C*h, tf32-rounded, K-permuted
__device__ float g_y1 [ (size_t)TOKENS * DMODEL ];   // tf32-rounded, K-permuted
__device__ float g_WTin [ DMODEL * DMODEL ];   // W_in^T, tf32, K-permuted
__device__ float g_WTcat[ 192 * DMODEL ];      // tf32, K-permuted
__device__ float g_WTso [ DMODEL * NSTATE ];   // tf32, K-permuted
__device__ float g_WTout[ DMODEL * DMODEL ];   // tf32, K-permuted
__device__ float g_bcat [ 192 ];
__device__ float g_chunkend[ BATCH * NCHUNKS * NSTATE ];
__device__ float g_hinit   [ BATCH * NCHUNKS * NSTATE ];

// ---------------- PTX helpers ----------------
__device__ __forceinline__ uint32_t smem_u32(const void* p) {
    uint32_t a;
    asm("{ .reg .u64 t; cvta.to.shared.u64 t, %1; cvt.u32.u64 %0, t; }" : "=r"(a) : "l"(p));
    return a;
}
__device__ __forceinline__ void cp16(uint32_t dst, const void* src) {
    asm volatile("cp.async.cg.shared.global [%0], [%1], 16;" :: "r"(dst), "l"(src));
}
#define CP_COMMIT()  asm volatile("cp.async.commit_group;" ::: "memory")
#define CP_WAIT0()   asm volatile("cp.async.wait_group 0;" ::: "memory")

__device__ __forceinline__ float f2tf32(float f) {
    uint32_t r;
    asm("cvt.rna.tf32.f32 %0, %1;" : "=r"(r) : "f"(f));
    return __uint_as_float(r);
}
__device__ __forceinline__ void mma8(float* d, uint32_t a0, uint32_t a1, uint32_t a2,
                                     uint32_t a3, uint32_t b0, uint32_t b1) {
    asm volatile(
        "mma.sync.aligned.m16n8k8.row.col.f32.tf32.tf32.f32 "
        "{%0,%1,%2,%3}, {%4,%5,%6,%7}, {%8,%9}, {%0,%1,%2,%3};"
        : "+f"(d[0]), "+f"(d[1]), "+f"(d[2]), "+f"(d[3])
        : "r"(a0), "r"(a1), "r"(a2), "r"(a3), "r"(b0), "r"(b1));
}

// ---------------- tf32 mma.sync GEMM ----------------
// C[M, N] = A[M, K] @ BT[:, K]^T + epilogue; BM=128 x BN, BK=32, 2-stage cp.async.
// A, BT tf32-rounded AND K-permuted (PERM8). Fragments load as LDS.64 pairs.
// EPI 0: + bias[col];  EPI 1: + bias[col]*aux;  EPI 2: + bias[col] + aux
// RND: round stored C to tf32;  DUP: also store full-precision to C2 (unpermuted)
// PRM: store C with K-permuted columns (C feeds a later GEMM as A)
template<int BN, int EPI, int RND, int DUP, int PRM>
__global__ void __launch_bounds__(256, 2)
mma_gemm(const float* __restrict__ A, const float* __restrict__ BT,
         float* __restrict__ C, float* __restrict__ C2,
         const float* __restrict__ bias, const float* __restrict__ aux,
         int K, int N) {
    constexpr int BM = 128, BK = 32, PAD = 40;
    constexpr int WN = BN / 4;       // warp tile N
    constexpr int NT = WN / 8;       // n-subtiles per warp
    constexpr int AITS = 4, BITS = BN / 32;
    extern __shared__ float smf[];
    float* As = smf;                       // 2 * BM * PAD
    float* Bs = smf + 2 * BM * PAD;        // 2 * BN * PAD

    const int tid  = threadIdx.x;
    const int lane = tid & 31;
    const int wid  = tid >> 5;
    const int wm   = wid & 1;
    const int wn   = wid >> 1;
    const int g    = lane >> 2;
    const int t    = lane & 3;
    const int m0   = blockIdx.y * BM;
    const int n0   = blockIdx.x * BN;
    const int S    = K / BK;

    // precomputed load-stage bases
    const int lrow = tid >> 3, lc4 = (tid & 7) * 4;
    const float* Asrc = A  + (size_t)(m0 + lrow) * K + lc4;
    const float* Bsrc = BT + (size_t)(n0 + lrow) * K + lc4;
    const uint32_t asu = smem_u32(As) + lrow * PAD * 4 + lc4 * 4;
    const uint32_t bsu = smem_u32(Bs) + lrow * PAD * 4 + lc4 * 4;

    auto load_stage = [&](int s) {
        int buf = s & 1;
        uint32_t dA = asu + buf * BM * PAD * 4;
        uint32_t dB = bsu + buf * BN * PAD * 4;
        const float* sA = Asrc + s * BK;
        const float* sB = Bsrc + s * BK;
        #pragma unroll
        for (int it = 0; it < AITS; it++)
            cp16(dA + it * 32 * PAD * 4, sA + (size_t)it * 32 * K);
        #pragma unroll
        for (int it = 0; it < BITS; it++)
            cp16(dB + it * 32 * PAD * 4, sB + (size_t)it * 32 * K);
        CP_COMMIT();
    };

    float d[4][NT][4];
    #pragma unroll
    for (int mt = 0; mt < 4; mt++)
        #pragma unroll
        for (int nt = 0; nt < NT; nt++)
            #pragma unroll
            for (int j = 0; j < 4; j++) d[mt][nt][j] = 0.0f;

    // fragment base pointers (uint2 = one (t, t+4) pair)
    const uint2* ap2base = reinterpret_cast<const uint2*>(As) + ((wm * 64 + g) * PAD) / 2 + t;
    const uint2* bp2base = reinterpret_cast<const uint2*>(Bs) + ((wn * WN + g) * PAD) / 2 + t;

    load_stage(0);

    for (int s = 0; s < S; s++) {
        CP_WAIT0();
        __syncthreads();
        int buf = s & 1;
        const uint2* ap2 = ap2base + buf * (BM * PAD / 2);
        const uint2* bp2 = bp2base + buf * (BN * PAD / 2);

        // start kk=0 fragment loads before issuing next-stage cp.asyncs
        uint2 U[4], V[4], W[NT];
        #pragma unroll
        for (int mt = 0; mt < 4; mt++) {
            U[mt] = ap2[mt * (16 * PAD / 2)];
            V[mt] = ap2[mt * (16 * PAD / 2) + 8 * PAD / 2];
        }
        #pragma unroll
        for (int nt = 0; nt < NT; nt++) W[nt] = bp2[nt * (8 * PAD / 2)];

        if (s + 1 < S) load_stage(s + 1);

        #pragma unroll
        for (int kk = 0; kk < 4; kk++) {
            uint2 U2[4], V2[4], W2[NT];
            if (kk < 3) {
                #pragma unroll
                for (int mt = 0; mt < 4; mt++) {
                    U2[mt] = ap2[mt * (16 * PAD / 2) + (kk + 1) * 4];
                    V2[mt] = ap2[mt * (16 * PAD / 2) + 8 * PAD / 2 + (kk + 1) * 4];
                }
                #pragma unroll
                for (int nt = 0; nt < NT; nt++) W2[nt] = bp2[nt * (8 * PAD / 2) + (kk + 1) * 4];
            }
            #pragma unroll
            for (int mt = 0; mt < 4; mt++)
                #pragma unroll
                for (int nt = 0; nt < NT; nt++)
                    mma8(d[mt][nt], U[mt].x, V[mt].x, U[mt].y, V[mt].y, W[nt].x, W[nt].y);
            if (kk < 3) {
                #pragma unroll
                for (int mt = 0; mt < 4; mt++) { U[mt] = U2[mt]; V[mt] = V2[mt]; }
                #pragma unroll
                for (int nt = 0; nt < NT; nt++) W[nt] = W2[nt];
            }
        }
    }

    // ---- epilogue ----
    #pragma unroll
    for (int mt = 0; mt < 4; mt++) {
        int row = m0 + wm * 64 + mt * 16 + g;
        #pragma unroll
        for (int nt = 0; nt < NT; nt++) {
            int col = n0 + wn * WN + nt * 8 + 2 * t;
            float2 b2 = *reinterpret_cast<const float2*>(bias + col);
            size_t off0 = (size_t)row * N + col;
            size_t off1 = (size_t)(row + 8) * N + col;
            float2 v0 = make_float2(d[mt][nt][0], d[mt][nt][1]);
            float2 v1 = make_float2(d[mt][nt][2], d[mt][nt][3]);
            if (EPI == 0) {
                v0.x += b2.x; v0.y += b2.y;
                v1.x += b2.x; v1.y += b2.y;
            } else if (EPI == 1) {
                float2 a0 = *reinterpret_cast<const float2*>(aux + off0);
                float2 a1 = *reinterpret_cast<const float2*>(aux + off1);
                v0.x += b2.x * a0.x; v0.y += b2.y * a0.y;
                v1.x += b2.x * a1.x; v1.y += b2.y * a1.y;
            } else {
                float2 a0 = *reinterpret_cast<const float2*>(aux + off0);
                float2 a1 = *reinterpret_cast<const float2*>(aux + off1);
                v0.x += b2.x + a0.x; v0.y += b2.y + a0.y;
                v1.x += b2.x + a1.x; v1.y += b2.y + a1.y;
            }
            if (DUP) {
                *reinterpret_cast<float2*>(C2 + off0) = v0;
                *reinterpret_cast<float2*>(C2 + off1) = v1;
            }
            if (RND) {
                v0.x = f2tf32(v0.x); v0.y = f2tf32(v0.y);
                v1.x = f2tf32(v1.x); v1.y = f2tf32(v1.y);
            }
            if (PRM) {
                int p0 = PERM8(col), p1 = PERM8(col + 1);
                C[(size_t)row * N + p0]       = v0.x;
                C[(size_t)row * N + p1]       = v0.y;
                C[(size_t)(row + 8) * N + p0] = v1.x;
                C[(size_t)(row + 8) * N + p1] = v1.y;
            } else {
                *reinterpret_cast<float2*>(C + off0) = v0;
                *reinterpret_cast<float2*>(C + off1) = v1;
            }
        }
    }
}

// ---------------- weight prep: transpose + concat + tf32 round + K-permute ----------------
__global__ void prep_weights(const float* __restrict__ W_in, const float* __restrict__ W_out,
                             const float* __restrict__ W_B, const float* __restrict__ W_C,
                             const float* __restrict__ W_xs, const float* __restrict__ W_so,
                             const float* __restrict__ b_B, const float* __restrict__ b_C) {
    int idx = blockIdx.x * 256 + threadIdx.x;
    if (idx < DMODEL * DMODEL) {
        int n = idx >> 9, k = idx & 511;
        int pk = PERM8(k);
        g_WTin [n * DMODEL + pk] = f2tf32(W_in [k * DMODEL + n]);
        g_WTout[n * DMODEL + pk] = f2tf32(W_out[k * DMODEL + n]);
    }
    if (idx < 192 * DMODEL) {
        int n = idx >> 9, k = idx & 511;
        float v;
        if (n < 64)       v = W_B [k * 64 + n];
        else if (n < 128) v = W_C [k * 64 + (n - 64)];
        else              v = W_xs[k * 64 + (n - 128)];
        g_WTcat[n * DMODEL + PERM8(k)] = f2tf32(v);
    }
    if (idx < DMODEL * NSTATE) {
        int d = idx >> 6, s = idx & 63;
        g_WTso[d * NSTATE + PERM8(s)] = f2tf32(W_so[s * DMODEL + d]);
    }
    if (idx < 192) g_bcat[idx] = (idx < 64) ? b_B[idx] : (idx < 128 ? b_C[idx - 64] : 0.0f);
}

// ---------------- LayerNorm (tf32-rounded, K-permuted out) ----------------
__global__ void ln_kernel(const float* __restrict__ x,
                          const float* __restrict__ gamma,
                          const float* __restrict__ beta) {
    int row = blockIdx.x;
    const float4* xr = reinterpret_cast<const float4*>(x) + (size_t)row * 128;
    int t = threadIdx.x;
    float4 v = xr[t];
    float s = v.x + v.y + v.z + v.w;
    float q = v.x*v.x + v.y*v.y + v.z*v.z + v.w*v.w;
    #pragma unroll
    for (int o = 16; o; o >>= 1) {
        s += __shfl_xor_sync(0xffffffffu, s, o);
        q += __shfl_xor_sync(0xffffffffu, q, o);
    }
    __shared__ float ss[4], qq[4];
    __shared__ float rowbuf[DMODEL];
    int w = t >> 5, l = t & 31;
    if (l == 0) { ss[w] = s; qq[w] = q; }
    __syncthreads();
    s = ss[0] + ss[1] + ss[2] + ss[3];
    q = qq[0] + qq[1] + qq[2] + qq[3];
    float mu  = s * (1.0f / DMODEL);
    float var = q * (1.0f / DMODEL) - mu * mu;
    float inv = rsqrtf(var + LN_EPS);
    float4 gv = reinterpret_cast<const float4*>(gamma)[t];
    float4 bv = reinterpret_cast<const float4*>(beta)[t];
    rowbuf[4*t + 0] = f2tf32((v.x - mu) * inv * gv.x + bv.x);
    rowbuf[4*t + 1] = f2tf32((v.y - mu) * inv * gv.y + bv.y);
    rowbuf[4*t + 2] = f2tf32((v.z - mu) * inv * gv.z + bv.z);
    rowbuf[4*t + 3] = f2tf32((v.w - mu) * inv * gv.w + bv.w);
    __syncthreads();
    float4 o;
    o.x = rowbuf[INV8(4*t + 0)];
    o.y = rowbuf[INV8(4*t + 1)];
    o.z = rowbuf[INV8(4*t + 2)];
    o.w = rowbuf[INV8(4*t + 3)];
    reinterpret_cast<float4*>(g_xn)[(size_t)row * 128 + t] = o;
}

// ---------------- chunked SSM scan ----------------
__global__ void scan_passA(const float* __restrict__ A_log) {
    int b = blockIdx.x >> 4;
    int c = blockIdx.x & 15;
    int n = threadIdx.x;
    float Ab = expf(-expf(A_log[n]));
    const float* base = g_bcx + (size_t)(b * SEQ + c * CHUNK) * 192;
    float h = 0.0f;
    #pragma unroll 8
    for (int t = 0; t < CHUNK; t++) {
        float Bv = base[(size_t)t * 192 + n];
        float xv = base[(size_t)t * 192 + 128 + n];
        h = fmaf(Ab, h, Bv * xv);
    }
    g_chunkend[(b * NCHUNKS + c) * NSTATE + n] = h;
}

__global__ void scan_passB(const float* __restrict__ A_log) {
    int idx = threadIdx.x;
    int b = idx / NSTATE;
    int n = idx % NSTATE;
    float AL = expf(-(float)CHUNK * expf(A_log[n]));
    float h = 0.0f;
    for (int c = 0; c < NCHUNKS; c++) {
        g_hinit[(b * NCHUNKS + c) * NSTATE + n] = h;
        h = fmaf(AL, h, g_chunkend[(b * NCHUNKS + c) * NSTATE + n]);
    }
}

// out: tf32-rounded, K-permuted (feeds GEMM3 A)
__global__ void scan_passC(const float* __restrict__ A_log) {
    int b = blockIdx.x >> 4;
    int c = blockIdx.x & 15;
    int n = threadIdx.x;
    int pn = PERM8(n);
    float Ab = expf(-expf(A_log[n]));
    const float* base = g_bcx + (size_t)(b * SEQ + c * CHUNK) * 192;
    float* out = g_ch + (size_t)(b * SEQ + c * CHUNK) * NSTATE;
    float h = g_hinit[(b * NCHUNKS + c) * NSTATE + n];
    #pragma unroll 8
    for (int t = 0; t < CHUNK; t++) {
        float Bv = base[(size_t)t * 192 + n];
        float Cv = base[(size_t)t * 192 + 64 + n];
        float xv = base[(size_t)t * 192 + 128 + n];
        h = fmaf(Ab, h, Bv * xv);
        out[(size_t)t * NSTATE + pn] = f2tf32(Cv * h);
    }
}

// ---------------- launch ----------------
extern "C" void kernel_launch(void* const* d_in, const int* in_sizes, int n_in,
                              void* d_out, int out_size) {
    const float* x        = (const float*)d_in[0];
    const float* ln_gamma = (const float*)d_in[1];
    const float* ln_beta  = (const float*)d_in[2];
    const float* W_in     = (const float*)d_in[3];
    const float* b_in     = (const float*)d_in[4];
    const float* W_xs     = (const float*)d_in[5];
    const float* W_B      = (const float*)d_in[6];
    const float* b_B      = (const float*)d_in[7];
    const float* W_C      = (const float*)d_in[8];
    const float* b_C      = (const float*)d_in[9];
    const float* A_log    = (const float*)d_in[10];
    const float* D_skip   = (const float*)d_in[11];
    const float* W_so     = (const float*)d_in[12];
    const float* W_out    = (const float*)d_in[13];
    const float* b_out    = (const float*)d_in[14];
    float* out = (float*)d_out;

    float* xn;    cudaGetSymbolAddress((void**)&xn,    g_xn);
    float* xp;    cudaGetSymbolAddress((void**)&xp,    g_xp);
    float* xpf;   cudaGetSymbolAddress((void**)&xpf,   g_xpf);
    float* bcx;   cudaGetSymbolAddress((void**)&bcx,   g_bcx);
    float* ch;    cudaGetSymbolAddress((void**)&ch,    g_ch);
    float* y1;    cudaGetSymbolAddress((void**)&y1,    g_y1);
    float* WTin;  cudaGetSymbolAddress((void**)&WTin,  g_WTin);
    float* WTcat; cudaGetSymbolAddress((void**)&WTcat, g_WTcat);
    float* WTso;  cudaGetSymbolAddress((void**)&WTso,  g_WTso);
    float* WTout; cudaGetSymbolAddress((void**)&WTout, g_WTout);
    float* bcat;  cudaGetSymbolAddress((void**)&bcat,  g_bcat);

    const int SMEM128 = 2 * (128 + 128) * 40 * 4;   // 81920
    const int SMEM64  = 2 * (128 +  64) * 40 * 4;   // 61440
    cudaFuncSetAttribute(mma_gemm<128, 0, 1, 1, 1>, cudaFuncAttributeMaxDynamicSharedMemorySize, SMEM128);
    cudaFuncSetAttribute(mma_gemm<128, 1, 1, 0, 1>, cudaFuncAttributeMaxDynamicSharedMemorySize, SMEM128);
    cudaFuncSetAttribute(mma_gemm<128, 2, 0, 0, 0>, cudaFuncAttributeMaxDynamicSharedMemorySize, SMEM128);
    cudaFuncSetAttribute(mma_gemm<64, 0, 0, 0, 0>,  cudaFuncAttributeMaxDynamicSharedMemorySize, SMEM64);

    // 1) weight prep
    prep_weights<<<(DMODEL * DMODEL + 255) / 256, 256>>>(W_in, W_out, W_B, W_C, W_xs, W_so, b_B, b_C);

    // 2) LayerNorm
    ln_kernel<<<TOKENS, 128>>>(x, ln_gamma, ln_beta);

    // 3) xp = xn @ W_in + b_in ; xp (tf32, permuted) + xpf (full, unpermuted)
    mma_gemm<128, 0, 1, 1, 1><<<dim3(4, 256), 256, SMEM128>>>(
        xn, WTin, xp, xpf, b_in, nullptr, DMODEL, DMODEL);

    // 4) [B|C|xs] = xp @ Wcat + bcat   (full precision, unpermuted -> scan)
    mma_gemm<64, 0, 0, 0, 0><<<dim3(3, 256), 256, SMEM64>>>(
        xp, WTcat, bcx, nullptr, bcat, nullptr, DMODEL, 192);

    // 5) chunked scan -> ch = tf32(C*h), permuted
    scan_passA<<<BATCH * NCHUNKS, NSTATE>>>(A_log);
    scan_passB<<<1, BATCH * NSTATE>>>(A_log);
    scan_passC<<<BATCH * NCHUNKS, NSTATE>>>(A_log);

    // 6) y1 = tf32(ch @ W_so + D_skip * xpf), permuted
    mma_gemm<128, 1, 1, 0, 1><<<dim3(4, 256), 256, SMEM128>>>(
        ch, WTso, y1, nullptr, D_skip, xpf, NSTATE, DMODEL);

    // 7) out = y1 @ W_out + b_out + x   (full precision, unpermuted)
    mma_gemm<128, 2, 0, 0, 0><<<dim3(4, 256), 256, SMEM128>>>(
        y1, WTout, out, nullptr, b_out, x, DMODEL, DMODEL);
}

// round 6
// speedup vs baseline: 1.0882x; 1.0095x over previous
#include <cuda_runtime.h>
#include <cstdint>
#include <math.h>

// Problem constants
#define BATCH 8
#define SEQ   4096
#define DMODEL 512
#define NSTATE 64
#define TOKENS (BATCH*SEQ)          // 32768
#define NCHUNKS 16
#define CHUNK  (SEQ/NCHUNKS)        // 256
#define LN_EPS 1e-3f

// ---------------- device scratch ----------------
__device__ float g_xn [ (size_t)TOKENS * DMODEL ];   // LN out, tf32-rounded
__device__ float g_xp [ (size_t)TOKENS * DMODEL ];   // in-proj, tf32-rounded (GEMM2 A)
__device__ float g_xpf[ (size_t)TOKENS * DMODEL ];   // in-proj, full precision (GEMM3 aux)
__device__ float g_bcx[ (size_t)TOKENS * 192 ];      // [B|C|xs], full precision (scan)
__device__ float g_ch [ (size_t)TOKENS * NSTATE ];   // C*h, tf32-rounded (GEMM3 A)
__device__ float g_y1 [ (size_t)TOKENS * DMODEL ];   // tf32-rounded (GEMM4 A)
__device__ float g_WTin [ DMODEL * DMODEL ];   // W_in^T, tf32
__device__ float g_WTcat[ 192 * DMODEL ];      // tf32
__device__ float g_WTso [ DMODEL * NSTATE ];   // tf32
__device__ float g_WTout[ DMODEL * DMODEL ];   // tf32
__device__ float g_bcat [ 192 ];
__device__ float g_chunkend[ BATCH * NCHUNKS * NSTATE ];
__device__ float g_hinit   [ BATCH * NCHUNKS * NSTATE ];

// ---------------- PTX helpers ----------------
__device__ __forceinline__ uint32_t smem_u32(const void* p) {
    uint32_t a;
    asm("{ .reg .u64 t; cvta.to.shared.u64 t, %1; cvt.u32.u64 %0, t; }" : "=r"(a) : "l"(p));
    return a;
}
__device__ __forceinline__ void cp16(uint32_t dst, const void* src) {
    asm volatile("cp.async.cg.shared.global [%0], [%1], 16;" :: "r"(dst), "l"(src));
}
#define CP_COMMIT()  asm volatile("cp.async.commit_group;" ::: "memory")
#define CP_WAIT0()   asm volatile("cp.async.wait_group 0;" ::: "memory")

__device__ __forceinline__ float f2tf32(float f) {
    uint32_t r;
    asm("cvt.rna.tf32.f32 %0, %1;" : "=r"(r) : "f"(f));
    return __uint_as_float(r);
}
__device__ __forceinline__ void ldsm4(uint32_t* r, uint32_t addr) {
    asm volatile("ldmatrix.sync.aligned.m8n8.x4.shared.b16 {%0,%1,%2,%3}, [%4];"
        : "=r"(r[0]), "=r"(r[1]), "=r"(r[2]), "=r"(r[3]) : "r"(addr));
}
__device__ __forceinline__ void mma8(float* d, uint32_t a0, uint32_t a1, uint32_t a2,
                                     uint32_t a3, uint32_t b0, uint32_t b1) {
    asm volatile(
        "mma.sync.aligned.m16n8k8.row.col.f32.tf32.tf32.f32 "
        "{%0,%1,%2,%3}, {%4,%5,%6,%7}, {%8,%9}, {%0,%1,%2,%3};"
        : "+f"(d[0]), "+f"(d[1]), "+f"(d[2]), "+f"(d[3])
        : "r"(a0), "r"(a1), "r"(a2), "r"(a3), "r"(b0), "r"(b1));
}

// ---------------- tf32 mma.sync GEMM (ldmatrix fragments) ----------------
// C[M, N] = A[M, K] @ BT[:, K]^T + epilogue; BM=128 x BN, BK=32, 2-stage cp.async.
// A, BT must be tf32-rounded. Fragments via ldmatrix.x4 (b16 trick for tf32).
// EPI 0: + bias[col];  EPI 1: + bias[col]*aux;  EPI 2: + bias[col] + aux
// RND: round stored C to tf32;  DUP: also store full-precision to C2
template<int BN, int EPI, int RND, int DUP>
__global__ void __launch_bounds__(256, 2)
mma_gemm(const float* __restrict__ A, const float* __restrict__ BT,
         float* __restrict__ C, float* __restrict__ C2,
         const float* __restrict__ bias, const float* __restrict__ aux,
         int K, int N) {
    constexpr int BM = 128, BK = 32, PAD = 36;
    constexpr int PAD4 = PAD * 4;
    constexpr int WN = BN / 4;       // warp tile N
    constexpr int NT = WN / 8;       // n-subtiles per warp
    constexpr int NP = NT / 2;       // B ldsm pairs per kk
    constexpr int AITS = 4, BITS = BN / 32;
    constexpr int ABUF = BM * PAD4, BBUF = BN * PAD4;
    extern __shared__ float smf[];
    float* As = smf;                       // 2 * BM * PAD
    float* Bs = smf + 2 * BM * PAD;        // 2 * BN * PAD

    const int tid  = threadIdx.x;
    const int lane = tid & 31;
    const int wid  = tid >> 5;
    const int wm   = wid & 1;
    const int wn   = wid >> 1;
    const int g    = lane >> 2;
    const int t    = lane & 3;
    const int m0   = blockIdx.y * BM;
    const int n0   = blockIdx.x * BN;
    const int S    = K / BK;

    // cp.async bases
    const int lrow = tid >> 3, lc4 = (tid & 7) * 4;
    const float* Asrc = A  + (size_t)(m0 + lrow) * K + lc4;
    const float* Bsrc = BT + (size_t)(n0 + lrow) * K + lc4;
    const uint32_t asu = smem_u32(As) + lrow * PAD4 + lc4 * 4;
    const uint32_t bsu = smem_u32(Bs) + lrow * PAD4 + lc4 * 4;

    auto load_stage = [&](int s) {
        int buf = s & 1;
        uint32_t dA = asu + buf * ABUF;
        uint32_t dB = bsu + buf * BBUF;
        const float* sA = Asrc + s * BK;
        const float* sB = Bsrc + s * BK;
        #pragma unroll
        for (int it = 0; it < AITS; it++)
            cp16(dA + it * 32 * PAD4, sA + (size_t)it * 32 * K);
        #pragma unroll
        for (int it = 0; it < BITS; it++)
            cp16(dB + it * 32 * PAD4, sB + (size_t)it * 32 * K);
        CP_COMMIT();
    };

    float d[4][NT][4];
    #pragma unroll
    for (int mt = 0; mt < 4; mt++)
        #pragma unroll
        for (int nt = 0; nt < NT; nt++)
            #pragma unroll
            for (int j = 0; j < 4; j++) d[mt][nt][j] = 0.0f;

    // ldmatrix per-lane base addresses
    // A: matrices [rows0-7 c0-3][rows8-15 c0-3][rows0-7 c4-7][rows8-15 c4-7]
    const uint32_t a_lane = smem_u32(As)
        + (wm * 64 + (lane & 15)) * PAD4 + (lane >> 4) * 16;
    // B: matrices [ntA c0-3][ntA c4-7][ntB c0-3][ntB c4-7] (ntB = ntA+1)
    const uint32_t b_lane = smem_u32(Bs)
        + (wn * WN + (lane & 7) + ((lane >> 4) & 1) * 8) * PAD4
        + ((lane >> 3) & 1) * 16;

    load_stage(0);

    for (int s = 0; s < S; s++) {
        CP_WAIT0();
        __syncthreads();
        int buf = s & 1;
        const uint32_t ab = a_lane + buf * ABUF;
        const uint32_t bb = b_lane + buf * BBUF;

        uint32_t af[2][4][4], bf[2][NP][4];
        #pragma unroll
        for (int mt = 0; mt < 4; mt++) ldsm4(af[0][mt], ab + mt * 16 * PAD4);
        #pragma unroll
        for (int np = 0; np < NP; np++) ldsm4(bf[0][np], bb + np * 16 * PAD4);

        if (s + 1 < S) load_stage(s + 1);

        #pragma unroll
        for (int kk = 0; kk < 4; kk++) {
            int cur = kk & 1, nxt = cur ^ 1;
            if (kk < 3) {
                #pragma unroll
                for (int mt = 0; mt < 4; mt++)
                    ldsm4(af[nxt][mt], ab + mt * 16 * PAD4 + (kk + 1) * 32);
                #pragma unroll
                for (int np = 0; np < NP; np++)
                    ldsm4(bf[nxt][np], bb + np * 16 * PAD4 + (kk + 1) * 32);
            }
            #pragma unroll
            for (int mt = 0; mt < 4; mt++)
                #pragma unroll
                for (int nt = 0; nt < NT; nt++) {
                    const uint32_t* bp = bf[cur][nt >> 1];
                    uint32_t b0 = (nt & 1) ? bp[2] : bp[0];
                    uint32_t b1 = (nt & 1) ? bp[3] : bp[1];
                    mma8(d[mt][nt], af[cur][mt][0], af[cur][mt][1],
                         af[cur][mt][2], af[cur][mt][3], b0, b1);
                }
        }
    }

    // ---- epilogue ----
    #pragma unroll
    for (int mt = 0; mt < 4; mt++) {
        int row = m0 + wm * 64 + mt * 16 + g;
        #pragma unroll
        for (int nt = 0; nt < NT; nt++) {
            int col = n0 + wn * WN + nt * 8 + 2 * t;
            float2 b2 = *reinterpret_cast<const float2*>(bias + col);
            size_t off0 = (size_t)row * N + col;
            size_t off1 = (size_t)(row + 8) * N + col;
            float2 v0 = make_float2(d[mt][nt][0], d[mt][nt][1]);
            float2 v1 = make_float2(d[mt][nt][2], d[mt][nt][3]);
            if (EPI == 0) {
                v0.x += b2.x; v0.y += b2.y;
                v1.x += b2.x; v1.y += b2.y;
            } else if (EPI == 1) {
                float2 a0 = *reinterpret_cast<const float2*>(aux + off0);
                float2 a1 = *reinterpret_cast<const float2*>(aux + off1);
                v0.x += b2.x * a0.x; v0.y += b2.y * a0.y;
                v1.x += b2.x * a1.x; v1.y += b2.y * a1.y;
            } else {
                float2 a0 = *reinterpret_cast<const float2*>(aux + off0);
                float2 a1 = *reinterpret_cast<const float2*>(aux + off1);
                v0.x += b2.x + a0.x; v0.y += b2.y + a0.y;
                v1.x += b2.x + a1.x; v1.y += b2.y + a1.y;
            }
            if (DUP) {
                *reinterpret_cast<float2*>(C2 + off0) = v0;
                *reinterpret_cast<float2*>(C2 + off1) = v1;
            }
            if (RND) {
                v0.x = f2tf32(v0.x); v0.y = f2tf32(v0.y);
                v1.x = f2tf32(v1.x); v1.y = f2tf32(v1.y);
            }
            *reinterpret_cast<float2*>(C + off0) = v0;
            *reinterpret_cast<float2*>(C + off1) = v1;
        }
    }
}

// ---------------- weight prep: transpose + concat + tf32 round ----------------
__global__ void prep_weights(const float* __restrict__ W_in, const float* __restrict__ W_out,
                             const float* __restrict__ W_B, const float* __restrict__ W_C,
                             const float* __restrict__ W_xs, const float* __restrict__ W_so,
                             const float* __restrict__ b_B, const float* __restrict__ b_C) {
    int idx = blockIdx.x * 256 + threadIdx.x;
    if (idx < DMODEL * DMODEL) {
        int n = idx >> 9, k = idx & 511;
        g_WTin [n * DMODEL + k] = f2tf32(W_in [k * DMODEL + n]);
        g_WTout[n * DMODEL + k] = f2tf32(W_out[k * DMODEL + n]);
    }
    if (idx < 192 * DMODEL) {
        int n = idx >> 9, k = idx & 511;
        float v;
        if (n < 64)       v = W_B [k * 64 + n];
        else if (n < 128) v = W_C [k * 64 + (n - 64)];
        else              v = W_xs[k * 64 + (n - 128)];
        g_WTcat[n * DMODEL + k] = f2tf32(v);
    }
    if (idx < DMODEL * NSTATE) {
        int d = idx >> 6, s = idx & 63;
        g_WTso[d * NSTATE + s] = f2tf32(W_so[s * DMODEL + d]);
    }
    if (idx < 192) g_bcat[idx] = (idx < 64) ? b_B[idx] : (idx < 128 ? b_C[idx - 64] : 0.0f);
}

// ---------------- LayerNorm (tf32-rounded out) ----------------
__global__ void ln_kernel(const float* __restrict__ x,
                          const float* __restrict__ gamma,
                          const float* __restrict__ beta) {
    int row = blockIdx.x;
    const float4* xr = reinterpret_cast<const float4*>(x) + (size_t)row * 128;
    int t = threadIdx.x;
    float4 v = xr[t];
    float s = v.x + v.y + v.z + v.w;
    float q = v.x*v.x + v.y*v.y + v.z*v.z + v.w*v.w;
    #pragma unroll
    for (int o = 16; o; o >>= 1) {
        s += __shfl_xor_sync(0xffffffffu, s, o);
        q += __shfl_xor_sync(0xffffffffu, q, o);
    }
    __shared__ float ss[4], qq[4];
    int w = t >> 5, l = t & 31;
    if (l == 0) { ss[w] = s; qq[w] = q; }
    __syncthreads();
    s = ss[0] + ss[1] + ss[2] + ss[3];
    q = qq[0] + qq[1] + qq[2] + qq[3];
    float mu  = s * (1.0f / DMODEL);
    float var = q * (1.0f / DMODEL) - mu * mu;
    float inv = rsqrtf(var + LN_EPS);
    float4 gv = reinterpret_cast<const float4*>(gamma)[t];
    float4 bv = reinterpret_cast<const float4*>(beta)[t];
    float4 o;
    o.x = f2tf32((v.x - mu) * inv * gv.x + bv.x);
    o.y = f2tf32((v.y - mu) * inv * gv.y + bv.y);
    o.z = f2tf32((v.z - mu) * inv * gv.z + bv.z);
    o.w = f2tf32((v.w - mu) * inv * gv.w + bv.w);
    reinterpret_cast<float4*>(g_xn)[(size_t)row * 128 + t] = o;
}

// ---------------- chunked SSM scan ----------------
__global__ void scan_passA(const float* __restrict__ A_log) {
    int b = blockIdx.x >> 4;
    int c = blockIdx.x & 15;
    int n = threadIdx.x;
    float Ab = expf(-expf(A_log[n]));
    const float* base = g_bcx + (size_t)(b * SEQ + c * CHUNK) * 192;
    float h = 0.0f;
    #pragma unroll 8
    for (int t = 0; t < CHUNK; t++) {
        float Bv = base[(size_t)t * 192 + n];
        float xv = base[(size_t)t * 192 + 128 + n];
        h = fmaf(Ab, h, Bv * xv);
    }
    g_chunkend[(b * NCHUNKS + c) * NSTATE + n] = h;
}

__global__ void scan_passB(const float* __restrict__ A_log) {
    int idx = threadIdx.x;
    int b = idx / NSTATE;
    int n = idx % NSTATE;
    float AL = expf(-(float)CHUNK * expf(A_log[n]));
    float h = 0.0f;
    for (int c = 0; c < NCHUNKS; c++) {
        g_hinit[(b * NCHUNKS + c) * NSTATE + n] = h;
        h = fmaf(AL, h, g_chunkend[(b * NCHUNKS + c) * NSTATE + n]);
    }
}

// out: tf32-rounded (feeds GEMM3 A)
__global__ void scan_passC(const float* __restrict__ A_log) {
    int b = blockIdx.x >> 4;
    int c = blockIdx.x & 15;
    int n = threadIdx.x;
    float Ab = expf(-expf(A_log[n]));
    const float* base = g_bcx + (size_t)(b * SEQ + c * CHUNK) * 192;
    float* out = g_ch + (size_t)(b * SEQ + c * CHUNK) * NSTATE;
    float h = g_hinit[(b * NCHUNKS + c) * NSTATE + n];
    #pragma unroll 8
    for (int t = 0; t < CHUNK; t++) {
        float Bv = base[(size_t)t * 192 + n];
        float Cv = base[(size_t)t * 192 + 64 + n];
        float xv = base[(size_t)t * 192 + 128 + n];
        h = fmaf(Ab, h, Bv * xv);
        out[(size_t)t * NSTATE + n] = f2tf32(Cv * h);
    }
}

// ---------------- launch ----------------
extern "C" void kernel_launch(void* const* d_in, const int* in_sizes, int n_in,
                              void* d_out, int out_size) {
    const float* x        = (const float*)d_in[0];
    const float* ln_gamma = (const float*)d_in[1];
    const float* ln_beta  = (const float*)d_in[2];
    const float* W_in     = (const float*)d_in[3];
    const float* b_in     = (const float*)d_in[4];
    const float* W_xs     = (const float*)d_in[5];
    const float* W_B      = (const float*)d_in[6];
    const float* b_B      = (const float*)d_in[7];
    const float* W_C      = (const float*)d_in[8];
    const float* b_C      = (const float*)d_in[9];
    const float* A_log    = (const float*)d_in[10];
    const float* D_skip   = (const float*)d_in[11];
    const float* W_so     = (const float*)d_in[12];
    const float* W_out    = (const float*)d_in[13];
    const float* b_out    = (const float*)d_in[14];
    float* out = (float*)d_out;

    float* xn;    cudaGetSymbolAddress((void**)&xn,    g_xn);
    float* xp;    cudaGetSymbolAddress((void**)&xp,    g_xp);
    float* xpf;   cudaGetSymbolAddress((void**)&xpf,   g_xpf);
    float* bcx;   cudaGetSymbolAddress((void**)&bcx,   g_bcx);
    float* ch;    cudaGetSymbolAddress((void**)&ch,    g_ch);
    float* y1;    cudaGetSymbolAddress((void**)&y1,    g_y1);
    float* WTin;  cudaGetSymbolAddress((void**)&WTin,  g_WTin);
    float* WTcat; cudaGetSymbolAddress((void**)&WTcat, g_WTcat);
    float* WTso;  cudaGetSymbolAddress((void**)&WTso,  g_WTso);
    float* WTout; cudaGetSymbolAddress((void**)&WTout, g_WTout);
    float* bcat;  cudaGetSymbolAddress((void**)&bcat,  g_bcat);

    const int SMEM128 = 2 * (128 + 128) * 36 * 4;   // 73728
    const int SMEM64  = 2 * (128 +  64) * 36 * 4;   // 55296
    cudaFuncSetAttribute(mma_gemm<128, 0, 1, 1>, cudaFuncAttributeMaxDynamicSharedMemorySize, SMEM128);
    cudaFuncSetAttribute(mma_gemm<128, 1, 1, 0>, cudaFuncAttributeMaxDynamicSharedMemorySize, SMEM128);
    cudaFuncSetAttribute(mma_gemm<128, 2, 0, 0>, cudaFuncAttributeMaxDynamicSharedMemorySize, SMEM128);
    cudaFuncSetAttribute(mma_gemm<64, 0, 0, 0>,  cudaFuncAttributeMaxDynamicSharedMemorySize, SMEM64);

    // 1) weight prep
    prep_weights<<<(DMODEL * DMODEL + 255) / 256, 256>>>(W_in, W_out, W_B, W_C, W_xs, W_so, b_B, b_C);

    // 2) LayerNorm
    ln_kernel<<<TOKENS, 128>>>(x, ln_gamma, ln_beta);

    // 3) xp = xn @ W_in + b_in ; xp (tf32) + xpf (full)
    mma_gemm<128, 0, 1, 1><<<dim3(4, 256), 256, SMEM128>>>(
        xn, WTin, xp, xpf, b_in, nullptr, DMODEL, DMODEL);

    // 4) [B|C|xs] = xp @ Wcat + bcat   (full precision -> scan)
    mma_gemm<64, 0, 0, 0><<<dim3(3, 256), 256, SMEM64>>>(
        xp, WTcat, bcx, nullptr, bcat, nullptr, DMODEL, 192);

    // 5) chunked scan -> ch = tf32(C*h)
    scan_passA<<<BATCH * NCHUNKS, NSTATE>>>(A_log);
    scan_passB<<<1, BATCH * NSTATE>>>(A_log);
    scan_passC<<<BATCH * NCHUNKS, NSTATE>>>(A_log);

    // 6) y1 = tf32(ch @ W_so + D_skip * xpf)
    mma_gemm<128, 1, 1, 0><<<dim3(4, 256), 256, SMEM128>>>(
        ch, WTso, y1, nullptr, D_skip, xpf, NSTATE, DMODEL);

    // 7) out = y1 @ W_out + b_out + x   (full precision)
    mma_gemm<128, 2, 0, 0><<<dim3(4, 256), 256, SMEM128>>>(
        y1, WTout, out, nullptr, b_out, x, DMODEL, DMODEL);
}

// round 7
// speedup vs baseline: 1.2386x; 1.1383x over previous
#include <cuda_runtime.h>
#include <cstdint>
#include <math.h>

// Problem constants
#define BATCH 8
#define SEQ   4096
#define DMODEL 512
#define NSTATE 64
#define TOKENS (BATCH*SEQ)          // 32768
#define NCHUNKS 64
#define CHUNK  (SEQ/NCHUNKS)        // 64
#define LN_EPS 1e-3f

// ---------------- device scratch ----------------
__device__ float g_xn [ (size_t)TOKENS * DMODEL ];   // LN out, tf32-rounded
__device__ float g_xp [ (size_t)TOKENS * DMODEL ];   // in-proj, tf32-rounded (GEMM2 A)
__device__ float g_xpf[ (size_t)TOKENS * DMODEL ];   // in-proj, full precision (GEMM3 aux)
__device__ float g_bcx[ (size_t)TOKENS * 192 ];      // [B|C|xs], full precision (scan)
__device__ float g_ch [ (size_t)TOKENS * NSTATE ];   // C*h, tf32-rounded (GEMM3 A)
__device__ float g_y1 [ (size_t)TOKENS * DMODEL ];   // tf32-rounded (GEMM4 A)
__device__ float g_WTin [ DMODEL * DMODEL ];   // W_in^T, tf32
__device__ float g_WTcat[ 192 * DMODEL ];      // tf32
__device__ float g_WTso [ DMODEL * NSTATE ];   // tf32
__device__ float g_WTout[ DMODEL * DMODEL ];   // tf32
__device__ float g_bcat [ 192 ];
__device__ float g_chunkend[ BATCH * NCHUNKS * NSTATE ];
__device__ float g_hinit   [ BATCH * NCHUNKS * NSTATE ];

// ---------------- PTX helpers ----------------
__device__ __forceinline__ uint32_t smem_u32(const void* p) {
    uint32_t a;
    asm("{ .reg .u64 t; cvta.to.shared.u64 t, %1; cvt.u32.u64 %0, t; }" : "=r"(a) : "l"(p));
    return a;
}
__device__ __forceinline__ void cp16(uint32_t dst, const void* src) {
    asm volatile("cp.async.cg.shared.global [%0], [%1], 16;" :: "r"(dst), "l"(src));
}
#define CP_COMMIT()  asm volatile("cp.async.commit_group;" ::: "memory")
#define CP_WAIT1()   asm volatile("cp.async.wait_group 1;" ::: "memory")

__device__ __forceinline__ float f2tf32(float f) {
    uint32_t r;
    asm("cvt.rna.tf32.f32 %0, %1;" : "=r"(r) : "f"(f));
    return __uint_as_float(r);
}
__device__ __forceinline__ void ldsm4(uint32_t* r, uint32_t addr) {
    asm volatile("ldmatrix.sync.aligned.m8n8.x4.shared.b16 {%0,%1,%2,%3}, [%4];"
        : "=r"(r[0]), "=r"(r[1]), "=r"(r[2]), "=r"(r[3]) : "r"(addr));
}
__device__ __forceinline__ void mma8(float* d, uint32_t a0, uint32_t a1, uint32_t a2,
                                     uint32_t a3, uint32_t b0, uint32_t b1) {
    asm volatile(
        "mma.sync.aligned.m16n8k8.row.col.f32.tf32.tf32.f32 "
        "{%0,%1,%2,%3}, {%4,%5,%6,%7}, {%8,%9}, {%0,%1,%2,%3};"
        : "+f"(d[0]), "+f"(d[1]), "+f"(d[2]), "+f"(d[3])
        : "r"(a0), "r"(a1), "r"(a2), "r"(a3), "r"(b0), "r"(b1));
}

// ---------------- tf32 mma.sync GEMM (ldmatrix fragments, 3-stage pipeline) ----------------
// C[M, N] = A[M, K] @ BT[:, K]^T + epilogue; BM=128 x BN, BK=32.
// 3-stage cp.async ring, wait_group 1 (one stage always in flight behind compute).
// EPI 0: + bias[col];  EPI 1: + bias[col]*aux;  EPI 2: + bias[col] + aux
// RND: round stored C to tf32;  DUP: also store full-precision to C2
template<int BN, int EPI, int RND, int DUP>
__global__ void __launch_bounds__(256, 2)
mma_gemm(const float* __restrict__ A, const float* __restrict__ BT,
         float* __restrict__ C, float* __restrict__ C2,
         const float* __restrict__ bias, const float* __restrict__ aux,
         int K, int N) {
    constexpr int BM = 128, BK = 32, PAD = 36, ST = 3;
    constexpr int PAD4 = PAD * 4;
    constexpr int WN = BN / 4;       // warp tile N
    constexpr int NT = WN / 8;       // n-subtiles per warp
    constexpr int NP = NT / 2;       // B ldsm pairs per kk
    constexpr int AITS = 4, BITS = BN / 32;
    constexpr int ABUF = BM * PAD4, BBUF = BN * PAD4;
    extern __shared__ float smf[];
    float* As = smf;                        // ST * BM * PAD
    float* Bs = smf + ST * BM * PAD;        // ST * BN * PAD

    const int tid  = threadIdx.x;
    const int lane = tid & 31;
    const int wid  = tid >> 5;
    const int wm   = wid & 1;
    const int wn   = wid >> 1;
    const int g    = lane >> 2;
    const int t    = lane & 3;
    const int m0   = blockIdx.y * BM;
    const int n0   = blockIdx.x * BN;
    const int S    = K / BK;

    // cp.async bases
    const int lrow = tid >> 3, lc4 = (tid & 7) * 4;
    const float* Asrc = A  + (size_t)(m0 + lrow) * K + lc4;
    const float* Bsrc = BT + (size_t)(n0 + lrow) * K + lc4;
    const uint32_t asu = smem_u32(As) + lrow * PAD4 + lc4 * 4;
    const uint32_t bsu = smem_u32(Bs) + lrow * PAD4 + lc4 * 4;

    auto load_stage = [&](int s) {
        int buf = s % ST;
        uint32_t dA = asu + buf * ABUF;
        uint32_t dB = bsu + buf * BBUF;
        const float* sA = Asrc + s * BK;
        const float* sB = Bsrc + s * BK;
        #pragma unroll
        for (int it = 0; it < AITS; it++)
            cp16(dA + it * 32 * PAD4, sA + (size_t)it * 32 * K);
        #pragma unroll
        for (int it = 0; it < BITS; it++)
            cp16(dB + it * 32 * PAD4, sB + (size_t)it * 32 * K);
        CP_COMMIT();
    };

    float d[4][NT][4];
    #pragma unroll
    for (int mt = 0; mt < 4; mt++)
        #pragma unroll
        for (int nt = 0; nt < NT; nt++)
            #pragma unroll
            for (int j = 0; j < 4; j++) d[mt][nt][j] = 0.0f;

    // ldmatrix per-lane base addresses
    const uint32_t a_lane = smem_u32(As)
        + (wm * 64 + (lane & 15)) * PAD4 + (lane >> 4) * 16;
    const uint32_t b_lane = smem_u32(Bs)
        + (wn * WN + (lane & 7) + ((lane >> 4) & 1) * 8) * PAD4
        + ((lane >> 3) & 1) * 16;

    load_stage(0);
    load_stage(1);

    for (int s = 0; s < S; s++) {
        CP_WAIT1();
        __syncthreads();
        int buf = s % ST;
        const uint32_t ab = a_lane + buf * ABUF;
        const uint32_t bb = b_lane + buf * BBUF;

        uint32_t af[2][4][4], bf[2][NP][4];
        #pragma unroll
        for (int mt = 0; mt < 4; mt++) ldsm4(af[0][mt], ab + mt * 16 * PAD4);
        #pragma unroll
        for (int np = 0; np < NP; np++) ldsm4(bf[0][np], bb + np * 16 * PAD4);

        if (s + 2 < S) load_stage(s + 2); else CP_COMMIT();

        #pragma unroll
        for (int kk = 0; kk < 4; kk++) {
            int cur = kk & 1, nxt = cur ^ 1;
            if (kk < 3) {
                #pragma unroll
                for (int mt = 0; mt < 4; mt++)
                    ldsm4(af[nxt][mt], ab + mt * 16 * PAD4 + (kk + 1) * 32);
                #pragma unroll
                for (int np = 0; np < NP; np++)
                    ldsm4(bf[nxt][np], bb + np * 16 * PAD4 + (kk + 1) * 32);
            }
            #pragma unroll
            for (int mt = 0; mt < 4; mt++)
                #pragma unroll
                for (int nt = 0; nt < NT; nt++) {
                    const uint32_t* bp = bf[cur][nt >> 1];
                    uint32_t b0 = (nt & 1) ? bp[2] : bp[0];
                    uint32_t b1 = (nt & 1) ? bp[3] : bp[1];
                    mma8(d[mt][nt], af[cur][mt][0], af[cur][mt][1],
                         af[cur][mt][2], af[cur][mt][3], b0, b1);
                }
        }
    }

    // ---- epilogue ----
    #pragma unroll
    for (int mt = 0; mt < 4; mt++) {
        int row = m0 + wm * 64 + mt * 16 + g;
        #pragma unroll
        for (int nt = 0; nt < NT; nt++) {
            int col = n0 + wn * WN + nt * 8 + 2 * t;
            float2 b2 = *reinterpret_cast<const float2*>(bias + col);
            size_t off0 = (size_t)row * N + col;
            size_t off1 = (size_t)(row + 8) * N + col;
            float2 v0 = make_float2(d[mt][nt][0], d[mt][nt][1]);
            float2 v1 = make_float2(d[mt][nt][2], d[mt][nt][3]);
            if (EPI == 0) {
                v0.x += b2.x; v0.y += b2.y;
                v1.x += b2.x; v1.y += b2.y;
            } else if (EPI == 1) {
                float2 a0 = *reinterpret_cast<const float2*>(aux + off0);
                float2 a1 = *reinterpret_cast<const float2*>(aux + off1);
                v0.x += b2.x * a0.x; v0.y += b2.y * a0.y;
                v1.x += b2.x * a1.x; v1.y += b2.y * a1.y;
            } else {
                float2 a0 = *reinterpret_cast<const float2*>(aux + off0);
                float2 a1 = *reinterpret_cast<const float2*>(aux + off1);
                v0.x += b2.x + a0.x; v0.y += b2.y + a0.y;
                v1.x += b2.x + a1.x; v1.y += b2.y + a1.y;
            }
            if (DUP) {
                *reinterpret_cast<float2*>(C2 + off0) = v0;
                *reinterpret_cast<float2*>(C2 + off1) = v1;
            }
            if (RND) {
                v0.x = f2tf32(v0.x); v0.y = f2tf32(v0.y);
                v1.x = f2tf32(v1.x); v1.y = f2tf32(v1.y);
            }
            *reinterpret_cast<float2*>(C + off0) = v0;
            *reinterpret_cast<float2*>(C + off1) = v1;
        }
    }
}

// ---------------- weight prep: transpose + concat + tf32 round ----------------
__global__ void prep_weights(const float* __restrict__ W_in, const float* __restrict__ W_out,
                             const float* __restrict__ W_B, const float* __restrict__ W_C,
                             const float* __restrict__ W_xs, const float* __restrict__ W_so,
                             const float* __restrict__ b_B, const float* __restrict__ b_C) {
    int idx = blockIdx.x * 256 + threadIdx.x;
    if (idx < DMODEL * DMODEL) {
        int n = idx >> 9, k = idx & 511;
        g_WTin [n * DMODEL + k] = f2tf32(W_in [k * DMODEL + n]);
        g_WTout[n * DMODEL + k] = f2tf32(W_out[k * DMODEL + n]);
    }
    if (idx < 192 * DMODEL) {
        int n = idx >> 9, k = idx & 511;
        float v;
        if (n < 64)       v = W_B [k * 64 + n];
        else if (n < 128) v = W_C [k * 64 + (n - 64)];
        else              v = W_xs[k * 64 + (n - 128)];
        g_WTcat[n * DMODEL + k] = f2tf32(v);
    }
    if (idx < DMODEL * NSTATE) {
        int d = idx >> 6, s = idx & 63;
        g_WTso[d * NSTATE + s] = f2tf32(W_so[s * DMODEL + d]);
    }
    if (idx < 192) g_bcat[idx] = (idx < 64) ? b_B[idx] : (idx < 128 ? b_C[idx - 64] : 0.0f);
}

// ---------------- LayerNorm (tf32-rounded out) ----------------
__global__ void ln_kernel(const float* __restrict__ x,
                          const float* __restrict__ gamma,
                          const float* __restrict__ beta) {
    int row = blockIdx.x;
    const float4* xr = reinterpret_cast<const float4*>(x) + (size_t)row * 128;
    int t = threadIdx.x;
    float4 v = xr[t];
    float s = v.x + v.y + v.z + v.w;
    float q = v.x*v.x + v.y*v.y + v.z*v.z + v.w*v.w;
    #pragma unroll
    for (int o = 16; o; o >>= 1) {
        s += __shfl_xor_sync(0xffffffffu, s, o);
        q += __shfl_xor_sync(0xffffffffu, q, o);
    }
    __shared__ float ss[4], qq[4];
    int w = t >> 5, l = t & 31;
    if (l == 0) { ss[w] = s; qq[w] = q; }
    __syncthreads();
    s = ss[0] + ss[1] + ss[2] + ss[3];
    q = qq[0] + qq[1] + qq[2] + qq[3];
    float mu  = s * (1.0f / DMODEL);
    float var = q * (1.0f / DMODEL) - mu * mu;
    float inv = rsqrtf(var + LN_EPS);
    float4 gv = reinterpret_cast<const float4*>(gamma)[t];
    float4 bv = reinterpret_cast<const float4*>(beta)[t];
    float4 o;
    o.x = f2tf32((v.x - mu) * inv * gv.x + bv.x);
    o.y = f2tf32((v.y - mu) * inv * gv.y + bv.y);
    o.z = f2tf32((v.z - mu) * inv * gv.z + bv.z);
    o.w = f2tf32((v.w - mu) * inv * gv.w + bv.w);
    reinterpret_cast<float4*>(g_xn)[(size_t)row * 128 + t] = o;
}

// ---------------- chunked SSM scan ----------------
__global__ void scan_passA(const float* __restrict__ A_log) {
    int b = blockIdx.x / NCHUNKS;
    int c = blockIdx.x % NCHUNKS;
    int n = threadIdx.x;
    float Ab = expf(-expf(A_log[n]));
    const float* base = g_bcx + (size_t)(b * SEQ + c * CHUNK) * 192;
    float h = 0.0f;
    #pragma unroll 8
    for (int t = 0; t < CHUNK; t++) {
        float Bv = base[(size_t)t * 192 + n];
        float xv = base[(size_t)t * 192 + 128 + n];
        h = fmaf(Ab, h, Bv * xv);
    }
    g_chunkend[(b * NCHUNKS + c) * NSTATE + n] = h;
}

__global__ void scan_passB(const float* __restrict__ A_log) {
    int idx = threadIdx.x;
    int b = idx / NSTATE;
    int n = idx % NSTATE;
    float AL = expf(-(float)CHUNK * expf(A_log[n]));
    float h = 0.0f;
    for (int c = 0; c < NCHUNKS; c++) {
        g_hinit[(b * NCHUNKS + c) * NSTATE + n] = h;
        h = fmaf(AL, h, g_chunkend[(b * NCHUNKS + c) * NSTATE + n]);
    }
}

// out: tf32-rounded (feeds GEMM3 A)
__global__ void scan_passC(const float* __restrict__ A_log) {
    int b = blockIdx.x / NCHUNKS;
    int c = blockIdx.x % NCHUNKS;
    int n = threadIdx.x;
    float Ab = expf(-expf(A_log[n]));
    const float* base = g_bcx + (size_t)(b * SEQ + c * CHUNK) * 192;
    float* out = g_ch + (size_t)(b * SEQ + c * CHUNK) * NSTATE;
    float h = g_hinit[(b * NCHUNKS + c) * NSTATE + n];
    #pragma unroll 8
    for (int t = 0; t < CHUNK; t++) {
        float Bv = base[(size_t)t * 192 + n];
        float Cv = base[(size_t)t * 192 + 64 + n];
        float xv = base[(size_t)t * 192 + 128 + n];
        h = fmaf(Ab, h, Bv * xv);
        out[(size_t)t * NSTATE + n] = f2tf32(Cv * h);
    }
}

// ---------------- launch ----------------
extern "C" void kernel_launch(void* const* d_in, const int* in_sizes, int n_in,
                              void* d_out, int out_size) {
    const float* x        = (const float*)d_in[0];
    const float* ln_gamma = (const float*)d_in[1];
    const float* ln_beta  = (const float*)d_in[2];
    const float* W_in     = (const float*)d_in[3];
    const float* b_in     = (const float*)d_in[4];
    const float* W_xs     = (const float*)d_in[5];
    const float* W_B      = (const float*)d_in[6];
    const float* b_B      = (const float*)d_in[7];
    const float* W_C      = (const float*)d_in[8];
    const float* b_C      = (const float*)d_in[9];
    const float* A_log    = (const float*)d_in[10];
    const float* D_skip   = (const float*)d_in[11];
    const float* W_so     = (const float*)d_in[12];
    const float* W_out    = (const float*)d_in[13];
    const float* b_out    = (const float*)d_in[14];
    float* out = (float*)d_out;

    float* xn;    cudaGetSymbolAddress((void**)&xn,    g_xn);
    float* xp;    cudaGetSymbolAddress((void**)&xp,    g_xp);
    float* xpf;   cudaGetSymbolAddress((void**)&xpf,   g_xpf);
    float* bcx;   cudaGetSymbolAddress((void**)&bcx,   g_bcx);
    float* ch;    cudaGetSymbolAddress((void**)&ch,    g_ch);
    float* y1;    cudaGetSymbolAddress((void**)&y1,    g_y1);
    float* WTin;  cudaGetSymbolAddress((void**)&WTin,  g_WTin);
    float* WTcat; cudaGetSymbolAddress((void**)&WTcat, g_WTcat);
    float* WTso;  cudaGetSymbolAddress((void**)&WTso,  g_WTso);
    float* WTout; cudaGetSymbolAddress((void**)&WTout, g_WTout);
    float* bcat;  cudaGetSymbolAddress((void**)&bcat,  g_bcat);

    const int SMEM128 = 3 * (128 + 128) * 36 * 4;   // 110592
    const int SMEM64  = 3 * (128 +  64) * 36 * 4;   //  82944
    cudaFuncSetAttribute(mma_gemm<128, 0, 1, 1>, cudaFuncAttributeMaxDynamicSharedMemorySize, SMEM128);
    cudaFuncSetAttribute(mma_gemm<128, 1, 1, 0>, cudaFuncAttributeMaxDynamicSharedMemorySize, SMEM128);
    cudaFuncSetAttribute(mma_gemm<128, 2, 0, 0>, cudaFuncAttributeMaxDynamicSharedMemorySize, SMEM128);
    cudaFuncSetAttribute(mma_gemm<64, 0, 0, 0>,  cudaFuncAttributeMaxDynamicSharedMemorySize, SMEM64);

    // 1) weight prep
    prep_weights<<<(DMODEL * DMODEL + 255) / 256, 256>>>(W_in, W_out, W_B, W_C, W_xs, W_so, b_B, b_C);

    // 2) LayerNorm
    ln_kernel<<<TOKENS, 128>>>(x, ln_gamma, ln_beta);

    // 3) xp = xn @ W_in + b_in ; xp (tf32) + xpf (full)
    mma_gemm<128, 0, 1, 1><<<dim3(4, 256), 256, SMEM128>>>(
        xn, WTin, xp, xpf, b_in, nullptr, DMODEL, DMODEL);

    // 4) [B|C|xs] = xp @ Wcat + bcat   (full precision -> scan)
    mma_gemm<64, 0, 0, 0><<<dim3(3, 256), 256, SMEM64>>>(
        xp, WTcat, bcx, nullptr, bcat, nullptr, DMODEL, 192);

    // 5) chunked scan -> ch = tf32(C*h)
    scan_passA<<<BATCH * NCHUNKS, NSTATE>>>(A_log);
    scan_passB<<<1, BATCH * NSTATE>>>(A_log);
    scan_passC<<<BATCH * NCHUNKS, NSTATE>>>(A_log);

    // 6) y1 = tf32(ch @ W_so + D_skip * xpf)
    mma_gemm<128, 1, 1, 0><<<dim3(4, 256), 256, SMEM128>>>(
        ch, WTso, y1, nullptr, D_skip, xpf, NSTATE, DMODEL);

    // 7) out = y1 @ W_out + b_out + x   (full precision)
    mma_gemm<128, 2, 0, 0><<<dim3(4, 256), 256, SMEM128>>>(
        y1, WTout, out, nullptr, b_out, x, DMODEL, DMODEL);
}